// round 2
// baseline (speedup 1.0000x reference)
#include <cuda_runtime.h>
#include <cuda_bf16.h>

#define COLS 4096
#define TPB  256
#define EPT  16   // elements per thread = 4 x float4

// Two-value block reduction: warp shfl tree, then 8-warp smem combine.
__device__ __forceinline__ float2 block_reduce2(float a, float b) {
    __shared__ float sa[8], sb[8];
    #pragma unroll
    for (int o = 16; o; o >>= 1) {
        a += __shfl_xor_sync(0xffffffffu, a, o);
        b += __shfl_xor_sync(0xffffffffu, b, o);
    }
    const int w = threadIdx.x >> 5;
    if ((threadIdx.x & 31) == 0) { sa[w] = a; sb[w] = b; }
    __syncthreads();
    if (threadIdx.x < 32) {
        a = (threadIdx.x < 8) ? sa[threadIdx.x] : 0.f;
        b = (threadIdx.x < 8) ? sb[threadIdx.x] : 0.f;
        #pragma unroll
        for (int o = 4; o; o >>= 1) {
            a += __shfl_xor_sync(0xffffffffu, a, o);
            b += __shfl_xor_sync(0xffffffffu, b, o);
        }
        if (threadIdx.x == 0) { sa[0] = a; sb[0] = b; }
    }
    __syncthreads();
    float2 r = make_float2(sa[0], sb[0]);
    __syncthreads();   // protect smem reuse across successive calls
    return r;
}

__device__ __forceinline__ float fsign(float x) {
    return (x > 0.f) ? 1.f : ((x < 0.f) ? -1.f : 0.f);
}

__global__ __launch_bounds__(TPB) void braq_order2_kernel(
    const float* __restrict__ x,
    const int* __restrict__ mask,
    float* __restrict__ out)
{
    const size_t base = (size_t)blockIdx.x * COLS;
    const float4* __restrict__ x4 = reinterpret_cast<const float4*>(x + base);
    const int4*   __restrict__ m4 = reinterpret_cast<const int4*>(mask + base);

    float v[EPT];          // masked values (0 outside mask)
    unsigned mb = 0;       // 16-bit mask
    float s = 0.f, c = 0.f;

    // ---- load + pass 1 partials: sum, count ----
    #pragma unroll
    for (int i = 0; i < 4; i++) {
        const int idx = threadIdx.x + i * TPB;      // coalesced 16B index
        float4 xv = __ldg(&x4[idx]);
        int4   mv = __ldg(&m4[idx]);
        const float xs[4] = {xv.x, xv.y, xv.z, xv.w};
        const int   ms[4] = {mv.x, mv.y, mv.z, mv.w};
        #pragma unroll
        for (int j = 0; j < 4; j++) {
            const bool m = (ms[j] != 0);
            const float val = m ? xs[j] : 0.f;
            v[i * 4 + j] = val;
            mb |= (m ? 1u : 0u) << (i * 4 + j);
            s += val;
            c += m ? 1.f : 0.f;
        }
    }

    float2 r1 = block_reduce2(s, c);
    const float cnt   = r1.y;
    const float inv   = (cnt > 0.f) ? (1.f / cnt) : 0.f;  // handles empty rows
    const float mean1 = r1.x * inv;

    // ---- pass 2: scale1 = mean |masked(v - mean1)| ----
    float a = 0.f;
    #pragma unroll
    for (int k = 0; k < EPT; k++) {
        const bool m = (mb >> k) & 1u;
        const float d = m ? (v[k] - mean1) : 0.f;
        a += fabsf(d);
    }
    const float scale1 = block_reduce2(a, 0.f).x * inv;

    // ---- pass 3: mean2 of residual2 = masked(v - (sign(d)*scale1 + mean1)) ----
    float s2 = 0.f;
    #pragma unroll
    for (int k = 0; k < EPT; k++) {
        const bool m = (mb >> k) & 1u;
        const float d  = v[k] - mean1;
        const float b1 = fsign(d) * scale1 + mean1;
        const float r2 = m ? (v[k] - b1) : 0.f;
        s2 += r2;
    }
    const float mean2 = block_reduce2(s2, 0.f).x * inv;

    // ---- pass 4: scale2 = mean |masked(residual2 - mean2)| ----
    float a2 = 0.f;
    #pragma unroll
    for (int k = 0; k < EPT; k++) {
        const bool m = (mb >> k) & 1u;
        const float d  = v[k] - mean1;
        const float b1 = fsign(d) * scale1 + mean1;
        const float r2 = v[k] - b1;
        const float c2 = m ? (r2 - mean2) : 0.f;
        a2 += fabsf(c2);
    }
    const float scale2 = block_reduce2(a2, 0.f).x * inv;

    // ---- output: masked (b1 + sign(c2)*scale2 + mean2), else 0 ----
    float4* __restrict__ o4 = reinterpret_cast<float4*>(out + base);
    #pragma unroll
    for (int i = 0; i < 4; i++) {
        float t[4];
        #pragma unroll
        for (int j = 0; j < 4; j++) {
            const int k = i * 4 + j;
            const bool m = (mb >> k) & 1u;
            const float d  = v[k] - mean1;
            const float b1 = fsign(d) * scale1 + mean1;
            const float c2 = (v[k] - b1) - mean2;
            t[j] = m ? (b1 + fsign(c2) * scale2 + mean2) : 0.f;
        }
        float4 ov; ov.x = t[0]; ov.y = t[1]; ov.z = t[2]; ov.w = t[3];
        o4[threadIdx.x + i * TPB] = ov;
    }
}

extern "C" void kernel_launch(void* const* d_in, const int* in_sizes, int n_in,
                              void* d_out, int out_size) {
    const float* x    = (const float*)d_in[0];
    const int*   mask = (const int*)d_in[1];
    float*       out  = (float*)d_out;
    const int rows = in_sizes[0] / COLS;   // 11008
    braq_order2_kernel<<<rows, TPB>>>(x, mask, out);
}